// round 8
// baseline (speedup 1.0000x reference)
#include <cuda_runtime.h>
#include <cuda_fp16.h>

#define D 64
#define MAX_NODES 50000
#define CAP 128            // bucket capacity per node (Poisson(16) degrees)
#define OVF_CAP 4096

// ---- scratch ----
__device__ __half g_support_h[MAX_NODES * D];       // X @ W in fp16 (6.4 MB)
__device__ int    g_cnt[MAX_NODES + 1];             // per-dst counters; [MAX_NODES] = novf
__device__ int2   g_bucket[MAX_NODES * CAP];        // (src, bitcast(w)) per dst (51.2 MB)
__device__ int3   g_ovf[OVF_CAP];                   // (dst, src, w) spill

// ---------------------------------------------------------------------------
// single-pass bucket fill
// ---------------------------------------------------------------------------
__global__ void fill_kernel(const int* __restrict__ edge_src,
                            const int* __restrict__ edge_dst,
                            const float* __restrict__ edge_weight, int n_edges) {
    int e = blockIdx.x * blockDim.x + threadIdx.x;
    if (e >= n_edges) return;
    int d = edge_dst[e];
    int slot = atomicAdd(&g_cnt[d], 1);
    if (slot < CAP) {
        g_bucket[d * CAP + slot] = make_int2(edge_src[e], __float_as_int(edge_weight[e]));
    } else {
        int o = atomicAdd(&g_cnt[MAX_NODES], 1);
        if (o < OVF_CAP)
            g_ovf[o] = make_int3(d, edge_src[e], __float_as_int(edge_weight[e]));
    }
}

// ---------------------------------------------------------------------------
// GEMM: support = X @ W, fp32 accumulate, fp16 store.
// 64-row x 64-col tile, 128 threads, 8x4 register blocking. 782 blocks.
// ---------------------------------------------------------------------------
#define TILE_R 64

__global__ __launch_bounds__(128) void gcn_gemm_kernel(
    const float* __restrict__ X, const float* __restrict__ W, int n_nodes) {
    __shared__ float Xt[D][TILE_R];  // 16 KB
    __shared__ float sW[D][D];       // 16 KB

    const int tid = threadIdx.x;
    const int row0 = blockIdx.x * TILE_R;

    // load W: 1024 float4 / 128 threads = 8 each
    {
        const float4* W4 = reinterpret_cast<const float4*>(W);
        float4* sW4 = reinterpret_cast<float4*>(&sW[0][0]);
#pragma unroll
        for (int j = 0; j < 8; j++) sW4[tid + j * 128] = W4[tid + j * 128];
    }
    // load X tile transposed: thread t -> row r = t&63, k-half h = t>>6
    {
        const int r = tid & 63;
        const int h = tid >> 6;
        const int grow = row0 + r;
#pragma unroll
        for (int j = 0; j < 8; j++) {
            const int k = (h * 8 + j) * 4;
            float4 v = make_float4(0.f, 0.f, 0.f, 0.f);
            if (grow < n_nodes)
                v = *reinterpret_cast<const float4*>(X + grow * D + k);
            Xt[k + 0][r] = v.x; Xt[k + 1][r] = v.y;
            Xt[k + 2][r] = v.z; Xt[k + 3][r] = v.w;
        }
    }
    __syncthreads();

    const int tc = (tid & 15) * 4;   // 16 col groups
    const int tr = (tid >> 4) * 8;   // 8 row groups of 8

    float acc[8][4] = {};
#pragma unroll 8
    for (int k = 0; k < D; k++) {
        const float4 xa = *reinterpret_cast<const float4*>(&Xt[k][tr]);
        const float4 xb = *reinterpret_cast<const float4*>(&Xt[k][tr + 4]);
        const float4 w  = *reinterpret_cast<const float4*>(&sW[k][tc]);
        acc[0][0] += xa.x * w.x; acc[0][1] += xa.x * w.y; acc[0][2] += xa.x * w.z; acc[0][3] += xa.x * w.w;
        acc[1][0] += xa.y * w.x; acc[1][1] += xa.y * w.y; acc[1][2] += xa.y * w.z; acc[1][3] += xa.y * w.w;
        acc[2][0] += xa.z * w.x; acc[2][1] += xa.z * w.y; acc[2][2] += xa.z * w.z; acc[2][3] += xa.z * w.w;
        acc[3][0] += xa.w * w.x; acc[3][1] += xa.w * w.y; acc[3][2] += xa.w * w.z; acc[3][3] += xa.w * w.w;
        acc[4][0] += xb.x * w.x; acc[4][1] += xb.x * w.y; acc[4][2] += xb.x * w.z; acc[4][3] += xb.x * w.w;
        acc[5][0] += xb.y * w.x; acc[5][1] += xb.y * w.y; acc[5][2] += xb.y * w.z; acc[5][3] += xb.y * w.w;
        acc[6][0] += xb.z * w.x; acc[6][1] += xb.z * w.y; acc[6][2] += xb.z * w.z; acc[6][3] += xb.z * w.w;
        acc[7][0] += xb.w * w.x; acc[7][1] += xb.w * w.y; acc[7][2] += xb.w * w.z; acc[7][3] += xb.w * w.w;
    }

#pragma unroll
    for (int i = 0; i < 8; i++) {
        const int grow = row0 + tr + i;
        if (grow < n_nodes) {
            __half2 h0 = __floats2half2_rn(acc[i][0], acc[i][1]);
            __half2 h1 = __floats2half2_rn(acc[i][2], acc[i][3]);
            uint2 pk = make_uint2(*reinterpret_cast<unsigned*>(&h0),
                                  *reinterpret_cast<unsigned*>(&h1));
            *reinterpret_cast<uint2*>(&g_support_h[grow * D + tc]) = pk;
        }
    }
}

// ---------------------------------------------------------------------------
// gather: one warp per node; lane l owns features [2l, 2l+1] (one half2).
// out[n] = b + sum_e w_e * support_h[src_e]   (+ overflow entries, if any)
// ---------------------------------------------------------------------------
__global__ __launch_bounds__(256) void gather_kernel(
    const float* __restrict__ b, float* __restrict__ out, int n_nodes) {
    int warp = (blockIdx.x * blockDim.x + threadIdx.x) >> 5;
    int lane = threadIdx.x & 31;
    if (warp >= n_nodes) return;

    int deg = g_cnt[warp];
    bool ovfl = deg > CAP;
    if (ovfl) deg = CAP;
    const int2* row = &g_bucket[warp * CAP];

    float2 a0 = make_float2(0.f, 0.f), a1 = make_float2(0.f, 0.f);
    float2 a2 = make_float2(0.f, 0.f), a3 = make_float2(0.f, 0.f);

    const __half2* sup2 = reinterpret_cast<const __half2*>(g_support_h);

    for (int p = 0; p < deg; p += 32) {
        int m = deg - p; if (m > 32) m = 32;
        int2 ed = make_int2(0, 0);
        if (lane < m) ed = row[p + lane];
        int j = 0;
        for (; j + 4 <= m; j += 4) {
            int s0 = __shfl_sync(0xffffffffu, ed.x, j + 0);
            int s1 = __shfl_sync(0xffffffffu, ed.x, j + 1);
            int s2 = __shfl_sync(0xffffffffu, ed.x, j + 2);
            int s3 = __shfl_sync(0xffffffffu, ed.x, j + 3);
            float w0 = __int_as_float(__shfl_sync(0xffffffffu, ed.y, j + 0));
            float w1 = __int_as_float(__shfl_sync(0xffffffffu, ed.y, j + 1));
            float w2 = __int_as_float(__shfl_sync(0xffffffffu, ed.y, j + 2));
            float w3 = __int_as_float(__shfl_sync(0xffffffffu, ed.y, j + 3));
            float2 v0 = __half22float2(sup2[s0 * (D / 2) + lane]);
            float2 v1 = __half22float2(sup2[s1 * (D / 2) + lane]);
            float2 v2 = __half22float2(sup2[s2 * (D / 2) + lane]);
            float2 v3 = __half22float2(sup2[s3 * (D / 2) + lane]);
            a0.x += w0 * v0.x; a0.y += w0 * v0.y;
            a1.x += w1 * v1.x; a1.y += w1 * v1.y;
            a2.x += w2 * v2.x; a2.y += w2 * v2.y;
            a3.x += w3 * v3.x; a3.y += w3 * v3.y;
        }
        for (; j < m; j++) {
            int s = __shfl_sync(0xffffffffu, ed.x, j);
            float wv = __int_as_float(__shfl_sync(0xffffffffu, ed.y, j));
            float2 v = __half22float2(sup2[s * (D / 2) + lane]);
            a0.x += wv * v.x; a0.y += wv * v.y;
        }
    }

    // overflow path: only taken if THIS node spilled (never for this dataset,
    // but deterministic + correct for any input).
    if (ovfl) {
        int novf = g_cnt[MAX_NODES];
        if (novf > OVF_CAP) novf = OVF_CAP;
        for (int o = 0; o < novf; o++) {
            int3 ed = g_ovf[o];
            if (ed.x == warp) {
                float wv = __int_as_float(ed.z);
                float2 v = __half22float2(sup2[ed.y * (D / 2) + lane]);
                a0.x += wv * v.x; a0.y += wv * v.y;
            }
        }
    }

    float2 bb = reinterpret_cast<const float2*>(b)[lane];
    float2 r;
    r.x = (a0.x + a1.x) + (a2.x + a3.x) + bb.x;
    r.y = (a0.y + a1.y) + (a2.y + a3.y) + bb.y;
    reinterpret_cast<float2*>(out + warp * D)[lane] = r;
}

// ---------------------------------------------------------------------------
extern "C" void kernel_launch(void* const* d_in, const int* in_sizes, int n_in,
                              void* d_out, int out_size) {
    const float* X    = (const float*)d_in[0];
    const int*   esrc = (const int*)d_in[1];
    const int*   edst = (const int*)d_in[2];
    const float* ew   = (const float*)d_in[3];
    const float* W    = (const float*)d_in[4];
    const float* b    = (const float*)d_in[5];
    float*       out  = (float*)d_out;

    int n_nodes = in_sizes[0] / D;
    int n_edges = in_sizes[1];

    static cudaStream_t s_side = nullptr;
    static cudaEvent_t s_fork = nullptr, s_join = nullptr;
    if (!s_side) {
        cudaStreamCreateWithFlags(&s_side, cudaStreamNonBlocking);
        cudaEventCreateWithFlags(&s_fork, cudaEventDisableTiming);
        cudaEventCreateWithFlags(&s_join, cudaEventDisableTiming);
    }

    // fork: GEMM concurrent with bucket build
    cudaEventRecord(s_fork, 0);
    cudaStreamWaitEvent(s_side, s_fork, 0);
    gcn_gemm_kernel<<<(n_nodes + TILE_R - 1) / TILE_R, 128, 0, s_side>>>(X, W, n_nodes);
    cudaEventRecord(s_join, s_side);

    // bucket build on main stream (single memset covers counters + ovf count)
    void* p_cnt = nullptr;
    cudaGetSymbolAddress(&p_cnt, g_cnt);
    cudaMemsetAsync(p_cnt, 0, (MAX_NODES + 1) * sizeof(int));
    fill_kernel<<<(n_edges + 255) / 256, 256>>>(esrc, edst, ew, n_edges);

    // join: gather needs buckets + support
    cudaStreamWaitEvent(0, s_join, 0);
    gather_kernel<<<(n_nodes * 32 + 255) / 256, 256>>>(b, out, n_nodes);
}

// round 9
// speedup vs baseline: 1.1849x; 1.1849x over previous
#include <cuda_runtime.h>
#include <cuda_fp16.h>
#include <cstdint>

#define D 64
#define MAX_NODES 50000
#define CAP 128            // bucket capacity per node (Poisson(16) degrees)
#define OVF_CAP 4096

// ---- scratch ----
__device__ __half g_support_h[MAX_NODES * D];       // X @ W in fp16 (6.4 MB)
__device__ int    g_cnt[MAX_NODES + 1];             // per-dst counters; [MAX_NODES] = novf
__device__ int2   g_bucket[MAX_NODES * CAP];        // (src, bitcast(w)) per dst (51.2 MB)
__device__ int3   g_ovf[OVF_CAP];                   // (dst, src, w) spill

// ---------------------------------------------------------------------------
// single-pass bucket fill
// ---------------------------------------------------------------------------
__global__ void fill_kernel(const int* __restrict__ edge_src,
                            const int* __restrict__ edge_dst,
                            const float* __restrict__ edge_weight, int n_edges) {
    int e = blockIdx.x * blockDim.x + threadIdx.x;
    if (e >= n_edges) return;
    int d = edge_dst[e];
    int slot = atomicAdd(&g_cnt[d], 1);
    if (slot < CAP) {
        g_bucket[d * CAP + slot] = make_int2(edge_src[e], __float_as_int(edge_weight[e]));
    } else {
        int o = atomicAdd(&g_cnt[MAX_NODES], 1);
        if (o < OVF_CAP)
            g_ovf[o] = make_int3(d, edge_src[e], __float_as_int(edge_weight[e]));
    }
}

// ---------------------------------------------------------------------------
// tensor-core GEMM: support_h = fp16( X @ W ), fp32 accumulate.
// Block = 128 rows x 64 cols, 256 threads (8 warps), warp = 16-row strip.
// mma.sync.m16n8k16 row.col f32.f16.f16.f32, ldmatrix from padded smem.
// ---------------------------------------------------------------------------
#define GR 128
#define LDA 72   // padded leading dim in halves (144B rows -> conflict-free ldmatrix)

__device__ __forceinline__ uint32_t smem_u32(const void* p) {
    return static_cast<uint32_t>(__cvta_generic_to_shared(p));
}

__device__ __forceinline__ void ldsm_x4(uint32_t& r0, uint32_t& r1,
                                        uint32_t& r2, uint32_t& r3, uint32_t addr) {
    asm volatile("ldmatrix.sync.aligned.m8n8.x4.shared.b16 {%0,%1,%2,%3}, [%4];"
                 : "=r"(r0), "=r"(r1), "=r"(r2), "=r"(r3) : "r"(addr));
}

__device__ __forceinline__ void ldsm_x2_trans(uint32_t& r0, uint32_t& r1, uint32_t addr) {
    asm volatile("ldmatrix.sync.aligned.m8n8.x2.trans.shared.b16 {%0,%1}, [%2];"
                 : "=r"(r0), "=r"(r1) : "r"(addr));
}

__device__ __forceinline__ void mma_16816(float* c, uint32_t a0, uint32_t a1,
                                          uint32_t a2, uint32_t a3,
                                          uint32_t b0, uint32_t b1) {
    asm volatile(
        "mma.sync.aligned.m16n8k16.row.col.f32.f16.f16.f32 "
        "{%0,%1,%2,%3}, {%4,%5,%6,%7}, {%8,%9}, {%0,%1,%2,%3};"
        : "+f"(c[0]), "+f"(c[1]), "+f"(c[2]), "+f"(c[3])
        : "r"(a0), "r"(a1), "r"(a2), "r"(a3), "r"(b0), "r"(b1));
}

__global__ __launch_bounds__(256) void gcn_gemm_hmma(
    const float* __restrict__ X, const float* __restrict__ W, int n_nodes) {
    __shared__ __align__(16) __half sA[GR][LDA];  // X tile fp16 (18 KB)
    __shared__ __align__(16) __half sB[D][LDA];   // W fp16      (9 KB)

    const int tid = threadIdx.x;
    const int lane = tid & 31;
    const int warp = tid >> 5;
    const int row0 = blockIdx.x * GR;

    // load + convert W (64x64): thread t -> row t>>2, cols (t&3)*16..+15
    {
        const int r = tid >> 2;
        const int c0 = (tid & 3) * 16;
#pragma unroll
        for (int j = 0; j < 4; j++) {
            float4 v = *reinterpret_cast<const float4*>(W + r * D + c0 + j * 4);
            *reinterpret_cast<__half2*>(&sB[r][c0 + j * 4])     = __floats2half2_rn(v.x, v.y);
            *reinterpret_cast<__half2*>(&sB[r][c0 + j * 4 + 2]) = __floats2half2_rn(v.z, v.w);
        }
    }
    // load + convert X tile (128x64): thread t -> row t>>1, half (t&1)*32
    {
        const int r = tid >> 1;
        const int c0 = (tid & 1) * 32;
        const int grow = row0 + r;
#pragma unroll
        for (int j = 0; j < 8; j++) {
            float4 v = make_float4(0.f, 0.f, 0.f, 0.f);
            if (grow < n_nodes)
                v = *reinterpret_cast<const float4*>(X + grow * D + c0 + j * 4);
            *reinterpret_cast<__half2*>(&sA[r][c0 + j * 4])     = __floats2half2_rn(v.x, v.y);
            *reinterpret_cast<__half2*>(&sA[r][c0 + j * 4 + 2]) = __floats2half2_rn(v.z, v.w);
        }
    }
    __syncthreads();

    const int mr = warp * 16;

    // ldmatrix lane addressing
    const int a_row = mr + (lane & 7) + ((lane & 8) ? 8 : 0);
    const int a_col = (lane & 16) ? 8 : 0;
    const int b_row = (lane & 15);

    float acc[8][4] = {};

#pragma unroll
    for (int ks = 0; ks < 4; ks++) {
        const int k0 = ks * 16;
        uint32_t a0, a1, a2, a3;
        ldsm_x4(a0, a1, a2, a3, smem_u32(&sA[a_row][k0 + a_col]));
#pragma unroll
        for (int n = 0; n < 8; n++) {
            uint32_t b0, b1;
            ldsm_x2_trans(b0, b1, smem_u32(&sB[k0 + b_row][n * 8]));
            mma_16816(acc[n], a0, a1, a2, a3, b0, b1);
        }
    }

    // epilogue: C layout -> half2 stores
    const int g = lane >> 2;       // row within 8-row group
    const int tg = lane & 3;       // col pair index
    const int r0g = row0 + mr + g;
    const int r1g = r0g + 8;
#pragma unroll
    for (int n = 0; n < 8; n++) {
        const int c = n * 8 + tg * 2;
        if (r0g < n_nodes)
            *reinterpret_cast<__half2*>(&g_support_h[r0g * D + c]) =
                __floats2half2_rn(acc[n][0], acc[n][1]);
        if (r1g < n_nodes)
            *reinterpret_cast<__half2*>(&g_support_h[r1g * D + c]) =
                __floats2half2_rn(acc[n][2], acc[n][3]);
    }
}

// ---------------------------------------------------------------------------
// gather: one warp per node; lane l owns features [2l, 2l+1] (one half2).
// out[n] = b + sum_e w_e * support_h[src_e]   (+ overflow entries, if any)
// ---------------------------------------------------------------------------
__global__ __launch_bounds__(256) void gather_kernel(
    const float* __restrict__ b, float* __restrict__ out, int n_nodes) {
    int warp = (blockIdx.x * blockDim.x + threadIdx.x) >> 5;
    int lane = threadIdx.x & 31;
    if (warp >= n_nodes) return;

    int deg = g_cnt[warp];
    bool ovfl = deg > CAP;
    if (ovfl) deg = CAP;
    const int2* row = &g_bucket[warp * CAP];

    float2 a0 = make_float2(0.f, 0.f), a1 = make_float2(0.f, 0.f);
    float2 a2 = make_float2(0.f, 0.f), a3 = make_float2(0.f, 0.f);

    const __half2* sup2 = reinterpret_cast<const __half2*>(g_support_h);

    for (int p = 0; p < deg; p += 32) {
        int m = deg - p; if (m > 32) m = 32;
        int2 ed = make_int2(0, 0);
        if (lane < m) ed = row[p + lane];
        int j = 0;
        for (; j + 4 <= m; j += 4) {
            int s0 = __shfl_sync(0xffffffffu, ed.x, j + 0);
            int s1 = __shfl_sync(0xffffffffu, ed.x, j + 1);
            int s2 = __shfl_sync(0xffffffffu, ed.x, j + 2);
            int s3 = __shfl_sync(0xffffffffu, ed.x, j + 3);
            float w0 = __int_as_float(__shfl_sync(0xffffffffu, ed.y, j + 0));
            float w1 = __int_as_float(__shfl_sync(0xffffffffu, ed.y, j + 1));
            float w2 = __int_as_float(__shfl_sync(0xffffffffu, ed.y, j + 2));
            float w3 = __int_as_float(__shfl_sync(0xffffffffu, ed.y, j + 3));
            float2 v0 = __half22float2(sup2[s0 * (D / 2) + lane]);
            float2 v1 = __half22float2(sup2[s1 * (D / 2) + lane]);
            float2 v2 = __half22float2(sup2[s2 * (D / 2) + lane]);
            float2 v3 = __half22float2(sup2[s3 * (D / 2) + lane]);
            a0.x += w0 * v0.x; a0.y += w0 * v0.y;
            a1.x += w1 * v1.x; a1.y += w1 * v1.y;
            a2.x += w2 * v2.x; a2.y += w2 * v2.y;
            a3.x += w3 * v3.x; a3.y += w3 * v3.y;
        }
        for (; j < m; j++) {
            int s = __shfl_sync(0xffffffffu, ed.x, j);
            float wv = __int_as_float(__shfl_sync(0xffffffffu, ed.y, j));
            float2 v = __half22float2(sup2[s * (D / 2) + lane]);
            a0.x += wv * v.x; a0.y += wv * v.y;
        }
    }

    if (ovfl) {
        int novf = g_cnt[MAX_NODES];
        if (novf > OVF_CAP) novf = OVF_CAP;
        for (int o = 0; o < novf; o++) {
            int3 ed = g_ovf[o];
            if (ed.x == warp) {
                float wv = __int_as_float(ed.z);
                float2 v = __half22float2(sup2[ed.y * (D / 2) + lane]);
                a0.x += wv * v.x; a0.y += wv * v.y;
            }
        }
    }

    float2 bb = reinterpret_cast<const float2*>(b)[lane];
    float2 r;
    r.x = (a0.x + a1.x) + (a2.x + a3.x) + bb.x;
    r.y = (a0.y + a1.y) + (a2.y + a3.y) + bb.y;
    reinterpret_cast<float2*>(out + warp * D)[lane] = r;
}

// ---------------------------------------------------------------------------
extern "C" void kernel_launch(void* const* d_in, const int* in_sizes, int n_in,
                              void* d_out, int out_size) {
    const float* X    = (const float*)d_in[0];
    const int*   esrc = (const int*)d_in[1];
    const int*   edst = (const int*)d_in[2];
    const float* ew   = (const float*)d_in[3];
    const float* W    = (const float*)d_in[4];
    const float* b    = (const float*)d_in[5];
    float*       out  = (float*)d_out;

    int n_nodes = in_sizes[0] / D;
    int n_edges = in_sizes[1];

    static cudaStream_t s_side = nullptr;
    static cudaEvent_t s_fork = nullptr, s_join = nullptr;
    if (!s_side) {
        cudaStreamCreateWithFlags(&s_side, cudaStreamNonBlocking);
        cudaEventCreateWithFlags(&s_fork, cudaEventDisableTiming);
        cudaEventCreateWithFlags(&s_join, cudaEventDisableTiming);
    }

    // fork: GEMM concurrent with bucket build
    cudaEventRecord(s_fork, 0);
    cudaStreamWaitEvent(s_side, s_fork, 0);
    gcn_gemm_hmma<<<(n_nodes + GR - 1) / GR, 256, 0, s_side>>>(X, W, n_nodes);
    cudaEventRecord(s_join, s_side);

    // bucket build on main stream (single memset covers counters + ovf count)
    void* p_cnt = nullptr;
    cudaGetSymbolAddress(&p_cnt, g_cnt);
    cudaMemsetAsync(p_cnt, 0, (MAX_NODES + 1) * sizeof(int));
    fill_kernel<<<(n_edges + 255) / 256, 256>>>(esrc, edst, ew, n_edges);

    // join: gather needs buckets + support
    cudaStreamWaitEvent(0, s_join, 0);
    gather_kernel<<<(n_nodes * 32 + 255) / 256, 256>>>(b, out, n_nodes);
}